// round 2
// baseline (speedup 1.0000x reference)
#include <cuda_runtime.h>

#define NROWS 65536
#define DIM   128
#define KCB   1024

// ---------------- device scratch (no allocations allowed) ----------------
__device__ float  g_csum2[KCB];
__device__ int    g_counts[KCB];
__device__ double g_loss;

// ---------------- helpers ----------------
__device__ __forceinline__ unsigned long long ffma2(unsigned long long a,
                                                    unsigned long long b,
                                                    unsigned long long c) {
    unsigned long long d;
    asm("fma.rn.f32x2 %0, %1, %2, %3;" : "=l"(d) : "l"(a), "l"(b), "l"(c));
    return d;
}

__device__ __forceinline__ float2 u2f2(unsigned long long v) {
    union { unsigned long long u; float2 f; } cvt;
    cvt.u = v;
    return cvt.f;
}

// ---------------- kernels ----------------
__global__ void vq_init() {
    int t = threadIdx.x;
    if (t < KCB) g_counts[t] = 0;
    if (t == 0) g_loss = 0.0;
}

__global__ void vq_csum2(const float* __restrict__ cb) {
    int k = blockIdx.x * blockDim.x + threadIdx.x;
    if (k < KCB) {
        float s = 0.0f;
        const float* row = cb + (size_t)k * DIM;
        #pragma unroll 8
        for (int d = 0; d < DIM; d++) {
            float v = row[d];
            s = __fadd_rn(s, __fmul_rn(v, v));   // unfused, mimic x**2 then sum
        }
        g_csum2[k] = s;
    }
}

// Main kernel: 512 blocks x 256 threads. Block = 128 rows x full K (16 chunks of 64).
// Thread tile: 8 rows x 4 codes, f32x2 packed along D.
#define AS_STRIDE 132          // floats per smem row (128 + 4 pad); = 33 ulonglong2

__global__ void __launch_bounds__(256)
vq_main(const float* __restrict__ in, const float* __restrict__ cb,
        float* __restrict__ out) {
    extern __shared__ float smem[];
    float* As      = smem;                          // 128*132 floats
    float* Bs      = smem + 128 * AS_STRIDE;        // 64*132 floats (reused for reduce)
    float* rows2_s = Bs + 64 * AS_STRIDE;           // 128
    float* csum_s  = rows2_s + 128;                 // 64
    int*   besti_s = (int*)(csum_s + 64);           // 128
    float* redv    = Bs;                            // 128*16 (alias, post-mainloop)
    int*   redi    = (int*)(Bs + 128 * 16);         // 128*16 (alias)

    const int tid = threadIdx.x;
    const int tx  = tid & 15;
    const int ty  = tid >> 4;
    const int rowBase = blockIdx.x * 128;

    // ---- load A tile (128 rows x 128 f32), row-major, padded stride ----
    {
        const float4* gin = (const float4*)(in + (size_t)rowBase * DIM);
        #pragma unroll
        for (int i = 0; i < 16; i++) {
            int idx = tid + i * 256;              // 0..4095
            int r = idx >> 5, c = idx & 31;
            ((float4*)(As + r * AS_STRIDE))[c] = gin[idx];
        }
    }
    __syncthreads();

    // ---- per-row sum of squares (sequential order, unfused like the ref) ----
    if (tid < 128) {
        float s = 0.0f;
        const float* ar = As + tid * AS_STRIDE;
        for (int d = 0; d < DIM; d++) {
            float v = ar[d];
            s = __fadd_rn(s, __fmul_rn(v, v));
        }
        rows2_s[tid] = s;
    }

    float minv[8];
    int   mini[8];
    #pragma unroll
    for (int r = 0; r < 8; r++) { minv[r] = 3.4e38f; mini[r] = 0; }

    // ---- main loop over 16 codebook chunks of 64 codes ----
    for (int ch = 0; ch < 16; ch++) {
        __syncthreads();                          // protect csum_s/Bs rewrite
        {
            const float4* gb = (const float4*)(cb + (size_t)ch * 64 * DIM);
            #pragma unroll
            for (int i = 0; i < 8; i++) {
                int idx = tid + i * 256;          // 0..2047
                int r = idx >> 5, c = idx & 31;
                ((float4*)(Bs + r * AS_STRIDE))[c] = gb[idx];
            }
            if (tid < 64) csum_s[tid] = g_csum2[ch * 64 + tid];
        }
        __syncthreads();

        unsigned long long acc[8][4];
        #pragma unroll
        for (int r = 0; r < 8; r++)
            #pragma unroll
            for (int j = 0; j < 4; j++) acc[r][j] = 0ULL;

        const ulonglong2* A2 = (const ulonglong2*)As;
        const ulonglong2* B2 = (const ulonglong2*)Bs;

        #pragma unroll 4
        for (int dq = 0; dq < 32; dq++) {         // 4 dims per iter
            ulonglong2 b[4];
            #pragma unroll
            for (int j = 0; j < 4; j++)
                b[j] = B2[(tx + 16 * j) * 33 + dq];
            #pragma unroll
            for (int r = 0; r < 8; r++) {
                ulonglong2 a = A2[(ty * 8 + r) * 33 + dq];
                #pragma unroll
                for (int j = 0; j < 4; j++) {
                    acc[r][j] = ffma2(a.x, b[j].x, acc[r][j]);
                    acc[r][j] = ffma2(a.y, b[j].y, acc[r][j]);
                }
            }
        }

        // chunk epilogue: running argmin (ascending index order, strict <)
        #pragma unroll
        for (int r = 0; r < 8; r++) {
            float t = rows2_s[ty * 8 + r];
            #pragma unroll
            for (int j = 0; j < 4; j++) {
                float2 s = u2f2(acc[r][j]);
                float dot = __fadd_rn(s.x, s.y);
                float dist = __fsub_rn(__fadd_rn(t, csum_s[tx + 16 * j]),
                                       __fmul_rn(2.0f, dot));
                int cod = ch * 64 + tx + 16 * j;
                if (dist < minv[r]) { minv[r] = dist; mini[r] = cod; }
            }
        }
    }

    // ---- cross-thread lexicographic argmin per row ----
    __syncthreads();                               // Bs now reusable
    #pragma unroll
    for (int r = 0; r < 8; r++) {
        int lr = ty * 8 + r;
        redv[lr * 16 + tx] = minv[r];
        redi[lr * 16 + tx] = mini[r];
    }
    __syncthreads();
    if (tid < 128) {
        float bv = 3.5e38f;
        int   bi = 0x7fffffff;
        #pragma unroll
        for (int t2 = 0; t2 < 16; t2++) {
            float v = redv[tid * 16 + t2];
            int   i2 = redi[tid * 16 + t2];
            if (v < bv || (v == bv && i2 < bi)) { bv = v; bi = i2; }
        }
        besti_s[tid] = bi;
        atomicAdd(&g_counts[bi], 1);
    }
    __syncthreads();

    // ---- quantized write + loss partial ----
    float ls = 0.0f;
    float* outq = out + 1;                         // quantized at element 1
    #pragma unroll 4
    for (int i = 0; i < 64; i++) {
        int idx = tid + i * 256;                   // 0..16383
        int lr = idx >> 7, d = idx & 127;
        float q = __ldg(&cb[(size_t)besti_s[lr] * DIM + d]);
        float x = As[lr * AS_STRIDE + d];
        float df = x - q;
        ls = fmaf(df, df, ls);
        outq[(size_t)(rowBase + lr) * DIM + d] = q;
    }
    #pragma unroll
    for (int o = 16; o; o >>= 1)
        ls += __shfl_down_sync(0xffffffffu, ls, o);
    if ((tid & 31) == 0) atomicAdd(&g_loss, (double)ls);

    // ---- one-hot encodings (region starts at elem 8388610: 8B-aligned) ----
    float2* enc2 = (float2*)(out + 2 + (size_t)NROWS * DIM);
    #pragma unroll 4
    for (int i = 0; i < 256; i++) {
        int idx = tid + i * 256;                   // 0..65535 float2s
        int lr = idx >> 9, p = idx & 511;
        int bi = besti_s[lr];
        int c0 = p * 2;
        float2 v;
        v.x = (c0     == bi) ? 1.0f : 0.0f;
        v.y = (c0 + 1 == bi) ? 1.0f : 0.0f;
        enc2[(size_t)(rowBase + lr) * 512 + p] = v;
    }
}

__global__ void vq_final(float* __restrict__ out) {
    __shared__ float sh[KCB];
    int t = threadIdx.x;
    float p = (float)g_counts[t] * (1.0f / 65536.0f);
    sh[t] = __fmul_rn(p, logf(__fadd_rn(p, 1e-10f)));
    __syncthreads();
    for (int s = 512; s; s >>= 1) {
        if (t < s) sh[t] += sh[t + s];
        __syncthreads();
    }
    if (t == 0) {
        out[1 + (size_t)NROWS * DIM] = expf(-sh[0]);     // perplexity
        double m = g_loss * (1.0 / ((double)NROWS * (double)DIM));
        out[0] = (float)(m + 0.25 * m);                  // loss = q + 0.25*e
    }
}

// ---------------- launch ----------------
extern "C" void kernel_launch(void* const* d_in, const int* in_sizes, int n_in,
                              void* d_out, int out_size) {
    const float* in = (const float*)d_in[0];
    const float* cb = (const float*)d_in[1];
    float* out = (float*)d_out;

    const size_t SMEM = (size_t)(128 * AS_STRIDE + 64 * AS_STRIDE + 128 + 64 + 128) * 4;
    cudaFuncSetAttribute(vq_main, cudaFuncAttributeMaxDynamicSharedMemorySize, (int)SMEM);

    vq_init<<<1, 1024>>>();
    vq_csum2<<<4, 256>>>(cb);
    vq_main<<<512, 256, SMEM>>>(in, cb, out);
    vq_final<<<1, 1024>>>(out);
}

// round 4
// speedup vs baseline: 1.1023x; 1.1023x over previous
#include <cuda_runtime.h>

#define NROWS 65536
#define DIM   128
#define KCB   1024

// ---------------- device scratch (no allocations allowed) ----------------
__device__ float  g_csum2[KCB];
__device__ int    g_counts[KCB];
__device__ double g_loss;

// ---------------- helpers ----------------
__device__ __forceinline__ unsigned long long ffma2(unsigned long long a,
                                                    unsigned long long b,
                                                    unsigned long long c) {
    unsigned long long d;
    asm("fma.rn.f32x2 %0, %1, %2, %3;" : "=l"(d) : "l"(a), "l"(b), "l"(c));
    return d;
}

__device__ __forceinline__ float2 u2f2(unsigned long long v) {
    union { unsigned long long u; float2 f; } cvt;
    cvt.u = v;
    return cvt.f;
}

// ---------------- prep: zero counts/loss + codebook row sums ----------------
__global__ void vq_prep(const float* __restrict__ cb) {
    int k = blockIdx.x * blockDim.x + threadIdx.x;
    if (k < KCB) {
        g_counts[k] = 0;
        float s = 0.0f;
        const float* row = cb + (size_t)k * DIM;
        #pragma unroll 8
        for (int d = 0; d < DIM; d++) {
            float v = row[d];
            s = __fadd_rn(s, __fmul_rn(v, v));   // unfused, mimic x**2 then sum
        }
        g_csum2[k] = s;
    }
    if (k == 0) g_loss = 0.0;
}

// Main kernel: 512 blocks x 256 threads, 2 CTAs/SM.
// Block = 128 rows x full K (16 chunks of 64). Thread tile: 8 rows x 4 codes,
// f32x2 packed along D.
// A tile UNPADDED (row = 32 ulonglong2; reads are per-warp broadcasts, so
// conflicts are irrelevant); B tile padded (stride 132 floats = 33 ulonglong2)
// for the 16-way-spread reads.
#define B_STRIDE 132

__global__ void __launch_bounds__(256, 2)
vq_main(const float* __restrict__ in, const float* __restrict__ cb,
        float* __restrict__ out) {
    extern __shared__ float smem[];
    float* As      = smem;                          // 128*128 floats (unpadded)
    float* Bs      = smem + 128 * 128;              // 64*132 floats (reused for reduce)
    float* rows2_s = Bs + 64 * B_STRIDE;            // 128
    float* csum_s  = rows2_s + 128;                 // 64
    int*   besti_s = (int*)(csum_s + 64);           // 128
    float* redv    = Bs;                            // 128*16 (alias, post-mainloop)
    int*   redi    = (int*)(Bs + 128 * 16);         // 128*16 (alias)

    const int tid = threadIdx.x;
    const int tx  = tid & 15;
    const int ty  = tid >> 4;
    const int rowBase = blockIdx.x * 128;

    // ---- load A tile (128 rows x 128 f32), row-major, unpadded ----
    {
        const float4* gin = (const float4*)(in + (size_t)rowBase * DIM);
        float4* As4 = (float4*)As;
        #pragma unroll
        for (int i = 0; i < 16; i++)
            As4[tid + i * 256] = gin[tid + i * 256];
    }
    __syncthreads();

    // ---- per-row sum of squares (sequential order, unfused like the ref) ----
    if (tid < 128) {
        float s = 0.0f;
        const float* ar = As + tid * 128;
        for (int d = 0; d < DIM; d++) {
            float v = ar[d];
            s = __fadd_rn(s, __fmul_rn(v, v));
        }
        rows2_s[tid] = s;
    }

    float minv[8];
    int   mini[8];
    #pragma unroll
    for (int r = 0; r < 8; r++) { minv[r] = 3.4e38f; mini[r] = 0; }

    // ---- main loop over 16 codebook chunks of 64 codes ----
    for (int ch = 0; ch < 16; ch++) {
        __syncthreads();                          // protect csum_s/Bs rewrite
        {
            const float4* gb = (const float4*)(cb + (size_t)ch * 64 * DIM);
            #pragma unroll
            for (int i = 0; i < 8; i++) {
                int idx = tid + i * 256;          // 0..2047
                int r = idx >> 5, c = idx & 31;
                ((float4*)(Bs + r * B_STRIDE))[c] = gb[idx];
            }
            if (tid < 64) csum_s[tid] = g_csum2[ch * 64 + tid];
        }
        __syncthreads();

        unsigned long long acc[8][4];
        #pragma unroll
        for (int r = 0; r < 8; r++)
            #pragma unroll
            for (int j = 0; j < 4; j++) acc[r][j] = 0ULL;

        // A row = 32 ulonglong2 (128 floats). Base: rows ty*8..ty*8+7.
        const ulonglong2* A2 = (const ulonglong2*)As + (size_t)(ty * 8) * 32;
        const ulonglong2* B2 = (const ulonglong2*)Bs;

        #pragma unroll 4
        for (int dq = 0; dq < 32; dq++) {         // 4 dims per iter
            ulonglong2 b[4];
            #pragma unroll
            for (int j = 0; j < 4; j++)
                b[j] = B2[(tx + 16 * j) * 33 + dq];
            #pragma unroll
            for (int r = 0; r < 8; r++) {
                ulonglong2 a = A2[r * 32 + dq];
                #pragma unroll
                for (int j = 0; j < 4; j++) {
                    acc[r][j] = ffma2(a.x, b[j].x, acc[r][j]);
                    acc[r][j] = ffma2(a.y, b[j].y, acc[r][j]);
                }
            }
        }

        // chunk epilogue: running argmin (ascending index order, strict <)
        #pragma unroll
        for (int r = 0; r < 8; r++) {
            float t = rows2_s[ty * 8 + r];
            #pragma unroll
            for (int j = 0; j < 4; j++) {
                float2 s = u2f2(acc[r][j]);
                float dot = __fadd_rn(s.x, s.y);
                float dist = __fsub_rn(__fadd_rn(t, csum_s[tx + 16 * j]),
                                       __fmul_rn(2.0f, dot));
                int cod = ch * 64 + tx + 16 * j;
                if (dist < minv[r]) { minv[r] = dist; mini[r] = cod; }
            }
        }
    }

    // ---- cross-thread lexicographic argmin per row ----
    __syncthreads();                               // Bs now reusable
    #pragma unroll
    for (int r = 0; r < 8; r++) {
        int lr = ty * 8 + r;
        redv[lr * 16 + tx] = minv[r];
        redi[lr * 16 + tx] = mini[r];
    }
    __syncthreads();
    if (tid < 128) {
        float bv = 3.5e38f;
        int   bi = 0x7fffffff;
        #pragma unroll
        for (int t2 = 0; t2 < 16; t2++) {
            float v = redv[tid * 16 + t2];
            int   i2 = redi[tid * 16 + t2];
            if (v < bv || (v == bv && i2 < bi)) { bv = v; bi = i2; }
        }
        besti_s[tid] = bi;
        atomicAdd(&g_counts[bi], 1);
    }
    __syncthreads();

    // ---- quantized write + loss partial ----
    float ls = 0.0f;
    float* outq = out + 1;                         // quantized at element 1
    #pragma unroll 4
    for (int i = 0; i < 64; i++) {
        int idx = tid + i * 256;                   // 0..16383
        int lr = idx >> 7, d = idx & 127;
        float q = __ldg(&cb[(size_t)besti_s[lr] * DIM + d]);
        float x = As[lr * 128 + d];
        float df = x - q;
        ls = fmaf(df, df, ls);
        outq[(size_t)(rowBase + lr) * DIM + d] = q;
    }
    #pragma unroll
    for (int o = 16; o; o >>= 1)
        ls += __shfl_down_sync(0xffffffffu, ls, o);
    if ((tid & 31) == 0) atomicAdd(&g_loss, (double)ls);

    // ---- one-hot encodings (region starts at elem 8388610: 8B-aligned) ----
    float2* enc2 = (float2*)(out + 2 + (size_t)NROWS * DIM);
    #pragma unroll 4
    for (int i = 0; i < 256; i++) {
        int idx = tid + i * 256;                   // 0..65535 float2s
        int lr = idx >> 9, p = idx & 511;
        int bi = besti_s[lr];
        int c0 = p * 2;
        float2 v;
        v.x = (c0     == bi) ? 1.0f : 0.0f;
        v.y = (c0 + 1 == bi) ? 1.0f : 0.0f;
        enc2[(size_t)(rowBase + lr) * 512 + p] = v;
    }
}

__global__ void vq_final(float* __restrict__ out) {
    __shared__ float sh[KCB];
    int t = threadIdx.x;
    float p = (float)g_counts[t] * (1.0f / 65536.0f);
    sh[t] = __fmul_rn(p, logf(__fadd_rn(p, 1e-10f)));
    __syncthreads();
    for (int s = 512; s; s >>= 1) {
        if (t < s) sh[t] += sh[t + s];
        __syncthreads();
    }
    if (t == 0) {
        out[1 + (size_t)NROWS * DIM] = expf(-sh[0]);     // perplexity
        double m = g_loss * (1.0 / ((double)NROWS * (double)DIM));
        out[0] = (float)(m + 0.25 * m);                  // loss = q + 0.25*e
    }
}

// ---------------- launch ----------------
extern "C" void kernel_launch(void* const* d_in, const int* in_sizes, int n_in,
                              void* d_out, int out_size) {
    const float* in = (const float*)d_in[0];
    const float* cb = (const float*)d_in[1];
    float* out = (float*)d_out;

    const size_t SMEM = (size_t)(128 * 128 + 64 * B_STRIDE + 128 + 64 + 128) * 4;
    cudaFuncSetAttribute(vq_main, cudaFuncAttributeMaxDynamicSharedMemorySize, (int)SMEM);

    vq_prep<<<4, 256>>>(cb);
    vq_main<<<512, 256, SMEM>>>(in, cb, out);
    vq_final<<<1, 1024>>>(out);
}